// round 8
// baseline (speedup 1.0000x reference)
#include <cuda_runtime.h>
#include <cuda_fp16.h>
#include <math.h>
#include <stdint.h>

typedef unsigned long long ull;

#define Bdim 4
#define Tdim 2048
#define Cdim 1024
#define Hdim 16
#define Ddim 64
#define CSdim 16
#define NTdim (Tdim/CSdim)          // 128 chunks
#define BTdim (Bdim*Tdim)           // 8192
#define BHT   (Bdim*Hdim*Tdim)      // 131072
#define EPSLN 1e-5f

// ---------------- device scratch (allocation-free rule) ----------------
__device__ float g_qkv[3][(size_t)BHT*Ddim];           // q,k,v  [b,h,t,d] fp32
__device__ float g_param[3][BHT];                      // theta/alpha/eta
__device__ float g_o[(size_t)BTdim*Cdim];              // raw scan output [b,t,c]
__device__ __half g_xh[(size_t)BTdim*Cdim];            // x hi/lo fp16 [M,K]
__device__ __half g_xl[(size_t)BTdim*Cdim];
__device__ __half g_wah[(size_t)3*Cdim*Cdim];          // W_attn^T fp16 [N,K]
__device__ __half g_wph[(size_t)Cdim*Cdim];            // W_proj^T fp16 [N,K]
__device__ __half g_oh[(size_t)BTdim*Cdim];            // o hi/lo fp16 [M,K]
__device__ __half g_ol[(size_t)BTdim*Cdim];

// ---------------- helpers ----------------
__device__ __forceinline__ uint32_t smem_u32(const void* p) {
    return (uint32_t)__cvta_generic_to_shared(p);
}
#define SWZ128(off) ((off) ^ (((off) >> 3) & 0x70))

__device__ __forceinline__ void cpasync16(uint32_t smem_dst, const void* gmem_src) {
    asm volatile("cp.async.ca.shared.global [%0], [%1], 16;" :: "r"(smem_dst), "l"(gmem_src) : "memory");
}
__device__ __forceinline__ void cpcommit()  { asm volatile("cp.async.commit_group;" ::: "memory"); }
__device__ __forceinline__ void cpwait1()   { asm volatile("cp.async.wait_group 1;" ::: "memory"); }
__device__ __forceinline__ void cpwait0()   { asm volatile("cp.async.wait_group 0;" ::: "memory"); }

__device__ __forceinline__ void ldmx4(uint32_t addr, uint32_t& r0, uint32_t& r1,
                                      uint32_t& r2, uint32_t& r3) {
    asm volatile("ldmatrix.sync.aligned.m8n8.x4.shared.b16 {%0,%1,%2,%3}, [%4];"
                 : "=r"(r0), "=r"(r1), "=r"(r2), "=r"(r3) : "r"(addr));
}
__device__ __forceinline__ void mma16816(float* c, uint32_t a0, uint32_t a1,
                                         uint32_t a2, uint32_t a3,
                                         uint32_t b0, uint32_t b1) {
    asm volatile("mma.sync.aligned.m16n8k16.row.col.f32.f16.f16.f32 "
                 "{%0,%1,%2,%3}, {%4,%5,%6,%7}, {%8,%9}, {%0,%1,%2,%3};"
                 : "+f"(c[0]), "+f"(c[1]), "+f"(c[2]), "+f"(c[3])
                 : "r"(a0), "r"(a1), "r"(a2), "r"(a3), "r"(b0), "r"(b1));
}

// ---------------------------------------------------------------------------
// convert_x: fp32 -> fp16 hi/lo split
// ---------------------------------------------------------------------------
__global__ __launch_bounds__(256) void convert_x(const float* __restrict__ x)
{
    size_t i = (size_t)blockIdx.x * 1024 + threadIdx.x * 4;
    float4 v = *(const float4*)(x + i);
    __half h0 = __float2half(v.x);
    __half h1 = __float2half(v.y);
    __half h2 = __float2half(v.z);
    __half h3 = __float2half(v.w);
    __half2* ph = (__half2*)(g_xh + i);
    __half2* pl = (__half2*)(g_xl + i);
    ph[0] = __half2(h0, h1);
    ph[1] = __half2(h2, h3);
    pl[0] = __half2(__float2half(v.x - __half2float(h0)),
                    __float2half(v.y - __half2float(h1)));
    pl[1] = __half2(__float2half(v.z - __half2float(h2)),
                    __float2half(v.w - __half2float(h3)));
}

// ---------------------------------------------------------------------------
// transpose W [K][N] fp32 -> WT fp16 [N][K]
// ---------------------------------------------------------------------------
__global__ __launch_bounds__(256) void transpose_w(const float* __restrict__ W,
                                                   __half* __restrict__ WTh,
                                                   int Nfull)
{
    __shared__ float tile[32][33];
    int n0 = blockIdx.x * 32, k0 = blockIdx.y * 32;
    int tx = threadIdx.x, ty = threadIdx.y;   // block (32,8)
#pragma unroll
    for (int i = 0; i < 32; i += 8)
        tile[ty + i][tx] = W[(size_t)(k0 + ty + i) * Nfull + n0 + tx];
    __syncthreads();
#pragma unroll
    for (int i = 0; i < 32; i += 8)
        WTh[(size_t)(n0 + ty + i) * Cdim + k0 + tx] = __float2half(tile[tx][ty + i]);
}

// ---------------------------------------------------------------------------
// HMMA GEMM: D = Ah@B^T + Al@B^T (fp16, fp32 accum). CTA 128x128, 256 thr,
// 3-stage cp.async pipeline, ONE barrier per k-chunk.
// ---------------------------------------------------------------------------
#define NCHUNK 32
#define TILE_B 16384

template<int MODE>
__global__ __launch_bounds__(256) void mma_gemm(const __half* __restrict__ Ah,
                                                const __half* __restrict__ Al,
                                                const __half* __restrict__ Bh,
                                                const float* __restrict__ bias,
                                                float* __restrict__ out)
{
    extern __shared__ char smem[];
    __shared__ float bias_s[128];
    uint32_t base = (smem_u32(smem) + 1023) & ~1023u;
    uint32_t Aof[3], Bof[3];
#pragma unroll
    for (int s = 0; s < 3; s++) { Aof[s] = base + s*2*TILE_B; Bof[s] = Aof[s] + TILE_B; }

    int tid = threadIdx.x;
    int wid = tid >> 5, lane = tid & 31;
    int wm = wid & 3, wn = wid >> 2;
    int row0 = blockIdx.y * 128, col0 = blockIdx.x * 128;

    if (tid < 128) bias_s[tid] = bias[col0 + tid];

    auto load_chunk = [&](int ci, int slot) {
        int p = ci >> 4;
        int kk0 = (ci & 15) * 64;
        const __half* As = p ? Al : Ah;
#pragma unroll
        for (int j = 0; j < 4; j++) {
            int id = tid + j * 256;
            int r = id >> 3, u = id & 7;
            uint32_t off = (uint32_t)(r * 128 + u * 16);
            cpasync16(Aof[slot] + SWZ128(off), As + (size_t)(row0 + r) * Cdim + kk0 + u * 8);
        }
#pragma unroll
        for (int j = 0; j < 4; j++) {
            int id = tid + j * 256;
            int r = id >> 3, u = id & 7;
            uint32_t off = (uint32_t)(r * 128 + u * 16);
            cpasync16(Bof[slot] + SWZ128(off), Bh + (size_t)(col0 + r) * Cdim + kk0 + u * 8);
        }
        cpcommit();
    };

    float acc[2][8][4];
#pragma unroll
    for (int mt = 0; mt < 2; mt++)
#pragma unroll
        for (int nt = 0; nt < 8; nt++)
#pragma unroll
            for (int q = 0; q < 4; q++) acc[mt][nt][q] = 0.f;

    int a_row = wm * 32 + (lane & 15);
    int a_kb  = (lane >> 4) * 16;
    int b_row = wn * 64 + (lane & 7) + ((lane >> 4) << 3);
    int b_kb  = ((lane >> 3) & 1) * 16;

    load_chunk(0, 0);
    load_chunk(1, 1);

    for (int ci = 0; ci < NCHUNK; ci++) {
        cpwait1();            // stage ci resident (<=1 group pending: ci+1)
        __syncthreads();      // all warps done with stage ci-1 -> its slot reusable
        if (ci + 2 < NCHUNK) load_chunk(ci + 2, (ci + 2) % 3);
        else                 cpcommit();   // keep group accounting uniform
        int s = ci % 3;

#pragma unroll
        for (int kk = 0; kk < 4; kk++) {
            uint32_t a[2][4];
#pragma unroll
            for (int mt = 0; mt < 2; mt++) {
                uint32_t off = (uint32_t)((a_row + mt*16) * 128 + kk*32 + a_kb);
                ldmx4(Aof[s] + SWZ128(off), a[mt][0], a[mt][1], a[mt][2], a[mt][3]);
            }
            uint32_t bfr[4][4];
#pragma unroll
            for (int nt2 = 0; nt2 < 4; nt2++) {
                uint32_t off = (uint32_t)((b_row + nt2*16) * 128 + kk*32 + b_kb);
                ldmx4(Bof[s] + SWZ128(off), bfr[nt2][0], bfr[nt2][1], bfr[nt2][2], bfr[nt2][3]);
            }
#pragma unroll
            for (int mt = 0; mt < 2; mt++)
#pragma unroll
                for (int nt = 0; nt < 8; nt++) {
                    int nt2 = nt >> 1, hi = (nt & 1) << 1;
                    mma16816(acc[mt][nt], a[mt][0], a[mt][1], a[mt][2], a[mt][3],
                             bfr[nt2][hi], bfr[nt2][hi + 1]);
                }
        }
    }

    int rbase = row0 + wm * 32 + (lane >> 2);
    if (MODE == 1) {
        int gcb = col0 + wn * 64;
        int kind = gcb >> 10;
        int h2 = (gcb & 1023) >> 6;
#pragma unroll
        for (int mt = 0; mt < 2; mt++) {
#pragma unroll
            for (int half = 0; half < 2; half++) {
                int r = rbase + mt*16 + half*8;
                int b = r >> 11, t = r & 2047;
                float* dst = &g_qkv[kind][(((size_t)b*Hdim + h2)*Tdim + t)*Ddim];
#pragma unroll
                for (int nt = 0; nt < 8; nt++) {
                    int cd = nt*8 + (lane & 3)*2;
                    float2 v;
                    v.x = acc[mt][nt][half*2 + 0] + bias_s[wn*64 + cd + 0];
                    v.y = acc[mt][nt][half*2 + 1] + bias_s[wn*64 + cd + 1];
                    *(float2*)(dst + cd) = v;
                }
            }
        }
    } else {
#pragma unroll
        for (int mt = 0; mt < 2; mt++) {
#pragma unroll
            for (int half = 0; half < 2; half++) {
                int r = rbase + mt*16 + half*8;
                float* dst = out + (size_t)r * Cdim + col0 + wn*64;
#pragma unroll
                for (int nt = 0; nt < 8; nt++) {
                    int cd = nt*8 + (lane & 3)*2;
                    float2 v;
                    v.x = acc[mt][nt][half*2 + 0] + bias_s[wn*64 + cd + 0];
                    v.y = acc[mt][nt][half*2 + 1] + bias_s[wn*64 + cd + 1];
                    *(float2*)(dst + cd) = v;
                }
            }
        }
    }
}

// ---------------------------------------------------------------------------
// normalize_qk: row-wise L2 normalization of q and k (fully parallel).
// One thread per 64-float row. 262144 rows total.
// ---------------------------------------------------------------------------
__global__ __launch_bounds__(256) void normalize_qk()
{
    int idx = blockIdx.x * 256 + threadIdx.x;
    int tensor = idx >> 17;                  // 131072 rows per tensor
    int row = idx & (BHT - 1);
    float* p = g_qkv[tensor] + (size_t)row * Ddim;
    float4 v[16];
#pragma unroll
    for (int i = 0; i < 16; i++) v[i] = *(const float4*)(p + i*4);
    float ss = 0.f;
#pragma unroll
    for (int i = 0; i < 16; i++)
        ss += v[i].x*v[i].x + v[i].y*v[i].y + v[i].z*v[i].z + v[i].w*v[i].w;
    float sc = 1.f / fmaxf(sqrtf(ss), 1e-12f);
#pragma unroll
    for (int i = 0; i < 16; i++) {
        v[i].x *= sc; v[i].y *= sc; v[i].z *= sc; v[i].w *= sc;
        *(float4*)(p + i*4) = v[i];
    }
}

// ---------------------------------------------------------------------------
// ln_split_o: LayerNorm(o) per (b,t,h) row + fp16 hi/lo split.
// One thread per 64-float row. 131072 rows.
// ---------------------------------------------------------------------------
__global__ __launch_bounds__(256) void ln_split_o(const float* __restrict__ w,
                                                  const float* __restrict__ bln)
{
    __shared__ float w_s[1024], b_s[1024];
    int tid = threadIdx.x;
#pragma unroll
    for (int i = tid; i < 1024; i += 256) { w_s[i] = w[i]; b_s[i] = bln[i]; }
    __syncthreads();

    int r = blockIdx.x * 256 + tid;          // row id; h = r & 15
    int h = r & 15;
    const float* src = g_o + (size_t)r * 64;
    float4 xv[16];
#pragma unroll
    for (int i = 0; i < 16; i++) xv[i] = *(const float4*)(src + i*4);
    float s = 0.f;
#pragma unroll
    for (int i = 0; i < 16; i++) s += xv[i].x + xv[i].y + xv[i].z + xv[i].w;
    float mu = s * (1.f/64.f);
    float vv = 0.f;
#pragma unroll
    for (int i = 0; i < 16; i++) {
        float a = xv[i].x-mu, b2 = xv[i].y-mu, c = xv[i].z-mu, d = xv[i].w-mu;
        vv += a*a + b2*b2 + c*c + d*d;
    }
    float rstd = rsqrtf(vv * (1.f/64.f) + EPSLN);

    size_t base = (size_t)r * 64;
    const float* wp = w_s + h*64;
    const float* bp = b_s + h*64;
#pragma unroll
    for (int g8 = 0; g8 < 8; g8++) {
        float y[8];
        float4 a = xv[g8*2], b4 = xv[g8*2+1];
        float xs[8] = {a.x,a.y,a.z,a.w,b4.x,b4.y,b4.z,b4.w};
#pragma unroll
        for (int j = 0; j < 8; j++)
            y[j] = (xs[j]-mu)*rstd*wp[g8*8+j] + bp[g8*8+j];
        uint4 uh, ul;
        __half hh[8], lo[8];
#pragma unroll
        for (int j = 0; j < 8; j++) {
            hh[j] = __float2half(y[j]);
            lo[j] = __float2half(y[j] - __half2float(hh[j]));
        }
        __half2 h01 = __halves2half2(hh[0],hh[1]), h23 = __halves2half2(hh[2],hh[3]);
        __half2 h45 = __halves2half2(hh[4],hh[5]), h67 = __halves2half2(hh[6],hh[7]);
        __half2 l01 = __halves2half2(lo[0],lo[1]), l23 = __halves2half2(lo[2],lo[3]);
        __half2 l45 = __halves2half2(lo[4],lo[5]), l67 = __halves2half2(lo[6],lo[7]);
        uh.x = *(uint32_t*)&h01; uh.y = *(uint32_t*)&h23;
        uh.z = *(uint32_t*)&h45; uh.w = *(uint32_t*)&h67;
        ul.x = *(uint32_t*)&l01; ul.y = *(uint32_t*)&l23;
        ul.z = *(uint32_t*)&l45; ul.w = *(uint32_t*)&l67;
        *(uint4*)(g_oh + base + g8*8) = uh;
        *(uint4*)(g_ol + base + g8*8) = ul;
    }
}

// ---------------------------------------------------------------------------
// K2: p = sigmoid(x @ W_param + b_param). 256 blocks x 32 rows.
// ---------------------------------------------------------------------------
__global__ __launch_bounds__(256) void param_kernel(const float* __restrict__ x,
                                                    const float* __restrict__ W,
                                                    const float* __restrict__ bias)
{
    __shared__ float xs[32][68];
    __shared__ float Ws[64][48];
    int tid = threadIdx.x;
    int row0 = blockIdx.x * 32;
    int r = tid >> 3, q = tid & 7;

    float acc[6];
#pragma unroll
    for (int j = 0; j < 6; j++) acc[j] = 0.f;

    for (int kt = 0; kt < Cdim; kt += 64) {
        int lr = tid >> 3;
        int lc0 = (tid & 7) * 8;
#pragma unroll
        for (int tt = 0; tt < 2; tt++) {
            float4 v = *(const float4*)(x + (size_t)(row0 + lr) * Cdim + kt + lc0 + tt*4);
            xs[lr][lc0 + tt*4 + 0] = v.x;
            xs[lr][lc0 + tt*4 + 1] = v.y;
            xs[lr][lc0 + tt*4 + 2] = v.z;
            xs[lr][lc0 + tt*4 + 3] = v.w;
        }
#pragma unroll
        for (int tt = 0; tt < 12; tt++) {
            int idx = tid + tt * 256;
            int wr = idx / 48, wc = idx % 48;
            Ws[wr][wc] = W[(size_t)(kt + wr) * 48 + wc];
        }
        __syncthreads();
#pragma unroll
        for (int kk = 0; kk < 64; kk++) {
            float xv = xs[r][kk];
#pragma unroll
            for (int j = 0; j < 6; j++) acc[j] += xv * Ws[kk][q + 8*j];
        }
        __syncthreads();
    }
    int grow = row0 + r;
    int b = grow / Tdim, t = grow % Tdim;
#pragma unroll
    for (int j = 0; j < 6; j++) {
        int col = q + 8*j;
        int h = col / 3, ii = col % 3;
        float v = acc[j] + bias[col];
        v = 1.f / (1.f + expf(-v));
        g_param[ii][((size_t)b*Hdim + h)*Tdim + t] = v;
    }
}

// ---------------------------------------------------------------------------
// K3: chunked Titans scan — q/k pre-normalized, o written raw.
// ---------------------------------------------------------------------------
__device__ __forceinline__ ull pk1(float v) {
    ull r; asm("mov.b64 %0, {%1, %1};" : "=l"(r) : "f"(v)); return r;
}
__device__ __forceinline__ ull fma2(ull a, ull b, ull c) {
    ull d; asm("fma.rn.f32x2 %0, %1, %2, %3;" : "=l"(d) : "l"(a), "l"(b), "l"(c)); return d;
}
__device__ __forceinline__ ull mul2(ull a, ull b) {
    ull d; asm("mul.rn.f32x2 %0, %1, %2;" : "=l"(d) : "l"(a), "l"(b)); return d;
}
__device__ __forceinline__ float2 upk(ull v) {
    float2 f; asm("mov.b64 {%0, %1}, %2;" : "=f"(f.x), "=f"(f.y) : "l"(v)); return f;
}

#define CHUNK_F (CSdim*Ddim)
#define BUF_F   (3*CHUNK_F + 48)

__global__ __launch_bounds__(512) void scan_kernel(const float* __restrict__ w,
                                                   const float* __restrict__ bln)
{
    __shared__ __align__(16) float buf[2][BUF_F];
    __shared__ float kh_s[16][64], dkh_s[16][64], o_s[16][64];
    __shared__ float w_s[64], b_s[64];

    int tid  = threadIdx.x;
    int e    = tid >> 3, g = tid & 7;
    int lane = tid & 31, wid = tid >> 5;
    int bh = blockIdx.x;
    int b  = bh >> 4, h = bh & 15;

    const float* qg = g_qkv[0] + (size_t)bh * Tdim * Ddim;
    const float* kg = g_qkv[1] + (size_t)bh * Tdim * Ddim;
    const float* vg = g_qkv[2] + (size_t)bh * Tdim * Ddim;
    const float* thg = g_param[0] + (size_t)bh * Tdim;
    const float* alg = g_param[1] + (size_t)bh * Tdim;
    const float* etg = g_param[2] + (size_t)bh * Tdim;

    if (tid < 64) { w_s[tid] = w[h*64 + tid]; b_s[tid] = bln[h*64 + tid]; }

    ull S2[4], m2[4];
#pragma unroll
    for (int i = 0; i < 4; i++) { S2[i] = 0ull; m2[i] = 0ull; }

#define PREFETCH(ci, dst)                                                     \
    do {                                                                      \
        int base4 = (ci) * (CHUNK_F/4);                                       \
        for (int idx = tid; idx < 780; idx += 512) {                          \
            if (idx < 256)                                                    \
                cpasync16(smem_u32((dst) + idx*4), (const float4*)kg + base4 + idx); \
            else if (idx < 512)                                               \
                cpasync16(smem_u32((dst) + CHUNK_F + (idx-256)*4),            \
                          (const float4*)qg + base4 + (idx-256));             \
            else if (idx < 768)                                               \
                cpasync16(smem_u32((dst) + 2*CHUNK_F + (idx-512)*4),          \
                          (const float4*)vg + base4 + (idx-512));             \
            else if (idx < 772)                                               \
                cpasync16(smem_u32((dst) + 3*CHUNK_F + (idx-768)*4),          \
                          (const float4*)(thg + (ci)*16) + (idx-768));        \
            else if (idx < 776)                                               \
                cpasync16(smem_u32((dst) + 3*CHUNK_F + 16 + (idx-772)*4),     \
                          (const float4*)(alg + (ci)*16) + (idx-772));        \
            else                                                              \
                cpasync16(smem_u32((dst) + 3*CHUNK_F + 32 + (idx-776)*4),     \
                          (const float4*)(etg + (ci)*16) + (idx-776));        \
        }                                                                     \
        cpcommit();                                                           \
    } while (0)

    PREFETCH(0, buf[0]);

    for (int ci = 0; ci < NTdim; ci++) {
        if (ci + 1 < NTdim) {
            PREFETCH(ci + 1, buf[(ci+1) & 1]);
            cpwait1();
        } else {
            cpwait0();
        }
        __syncthreads();

        float* Kp = buf[ci & 1];
        float* Qp = Kp + CHUNK_F;
        float* Vp = Kp + 2*CHUNK_F;
        float* TH = Kp + 3*CHUNK_F;
        float* AL = TH + 16;
        float* ET = TH + 32;

        // kh = k @ S (packed partials + width-8 reduce)
#pragma unroll
        for (int c = 0; c < 16; c++) {
            ulonglong2 ka = *(const ulonglong2*)&Kp[c*64 + 8*g];
            ulonglong2 kb = *(const ulonglong2*)&Kp[c*64 + 8*g + 4];
            ull p2 = 0ull;
            p2 = fma2(ka.x, S2[0], p2);
            p2 = fma2(ka.y, S2[1], p2);
            p2 = fma2(kb.x, S2[2], p2);
            p2 = fma2(kb.y, S2[3], p2);
            float2 pf = upk(p2);
            float p = pf.x + pf.y;
            p += __shfl_xor_sync(0xffffffffu, p, 1);
            p += __shfl_xor_sync(0xffffffffu, p, 2);
            p += __shfl_xor_sync(0xffffffffu, p, 4);
            if (g == 0) kh_s[c][e] = p;
        }
        __syncthreads();

        // LN fwd + bwd per row
        {
            int c = wid;
            float x0 = kh_s[c][lane], x1 = kh_s[c][lane+32];
            float s = x0 + x1;
#pragma unroll
            for (int off = 16; off; off >>= 1) s += __shfl_xor_sync(0xffffffffu, s, off);
            float mu = s * (1.f/64.f);
            float xc0 = x0 - mu, xc1 = x1 - mu;
            float vv = xc0*xc0 + xc1*xc1;
#pragma unroll
            for (int off = 16; off; off >>= 1) vv += __shfl_xor_sync(0xffffffffu, vv, off);
            float rstd = rsqrtf(vv * (1.f/64.f) + EPSLN);
            float xh0 = xc0 * rstd, xh1 = xc1 * rstd;
            float w0 = w_s[lane], w1 = w_s[lane+32];
            float y0 = xh0*w0 + b_s[lane], y1 = xh1*w1 + b_s[lane+32];
            float dy0 = 2.f*(y0 - Vp[c*64 + lane]);
            float dy1 = 2.f*(y1 - Vp[c*64 + lane + 32]);
            float wdy0 = dy0*w0, wdy1 = dy1*w1;
            float c1 = xh0*wdy0 + xh1*wdy1;
            float c2 = wdy0 + wdy1;
#pragma unroll
            for (int off = 16; off; off >>= 1) {
                c1 += __shfl_xor_sync(0xffffffffu, c1, off);
                c2 += __shfl_xor_sync(0xffffffffu, c2, off);
            }
            c1 *= (1.f/64.f); c2 *= (1.f/64.f);
            dkh_s[c][lane]    = (wdy0 - xh0*c1 - c2) * rstd;
            dkh_s[c][lane+32] = (wdy1 - xh1*c1 - c2) * rstd;
        }
        __syncthreads();

        // token scan: state in packed registers
#pragma unroll 4
        for (int c = 0; c < 16; c++) {
            float th = TH[c], al = AL[c], et = ET[c];
            float dk = dkh_s[c][e];
            ulonglong2 ka = *(const ulonglong2*)&Kp[c*64 + 8*g];
            ulonglong2 kb = *(const ulonglong2*)&Kp[c*64 + 8*g + 4];
            ulonglong2 qa = *(const ulonglong2*)&Qp[c*64 + 8*g];
            ulonglong2 qb = *(const ulonglong2*)&Qp[c*64 + 8*g + 4];
            ull kp[4] = {ka.x, ka.y, kb.x, kb.y};
            ull qp[4] = {qa.x, qa.y, qb.x, qb.y};
            ull et2  = pk1(et);
            ull oma2 = pk1(1.f - al);
            ull ntd2 = pk1(-th * dk);
            ull po2 = 0ull;
#pragma unroll
            for (int j = 0; j < 4; j++) {
                m2[j] = fma2(et2, m2[j], mul2(ntd2, kp[j]));
                S2[j] = fma2(oma2, S2[j], m2[j]);
                po2   = fma2(qp[j], S2[j], po2);
            }
            float2 pf = upk(po2);
            float po = pf.x + pf.y;
            po += __shfl_xor_sync(0xffffffffu, po, 1);
            po += __shfl_xor_sync(0xffffffffu, po, 2);
            po += __shfl_xor_sync(0xffffffffu, po, 4);
            if (g == 0) o_s[c][e] = po;
        }
        __syncthreads();

        // coalesced raw o write: warp wid handles row wid
        {
            int c = wid;
            int t = ci*16 + c;
            float2 v = *(const float2*)&o_s[c][lane*2];
            *(float2*)(g_o + ((size_t)b*Tdim + t)*Cdim + h*64 + lane*2) = v;
        }
    }
#undef PREFETCH
}

// ---------------------------------------------------------------------------
extern "C" void kernel_launch(void* const* d_in, const int* in_sizes, int n_in,
                              void* d_out, int out_size)
{
    const float* x       = (const float*)d_in[0];
    const float* W_attn  = (const float*)d_in[1];
    const float* b_attn  = (const float*)d_in[2];
    const float* W_param = (const float*)d_in[3];
    const float* b_param = (const float*)d_in[4];
    const float* W_proj  = (const float*)d_in[5];
    const float* b_proj  = (const float*)d_in[6];
    const float* w       = (const float*)d_in[7];
    const float* bb      = (const float*)d_in[8];
    float* out = (float*)d_out;

    const int SMEM_MMA = 1024 + 6*TILE_B;   // 3-stage, ~97KB
    cudaFuncSetAttribute(mma_gemm<1>, cudaFuncAttributeMaxDynamicSharedMemorySize, SMEM_MMA);
    cudaFuncSetAttribute(mma_gemm<0>, cudaFuncAttributeMaxDynamicSharedMemorySize, SMEM_MMA);

    __half *xh, *xl, *wah, *wph, *oh, *ol;
    cudaGetSymbolAddress((void**)&xh,  g_xh);
    cudaGetSymbolAddress((void**)&xl,  g_xl);
    cudaGetSymbolAddress((void**)&wah, g_wah);
    cudaGetSymbolAddress((void**)&wph, g_wph);
    cudaGetSymbolAddress((void**)&oh,  g_oh);
    cudaGetSymbolAddress((void**)&ol,  g_ol);

    convert_x<<<(BTdim*Cdim)/1024, 256>>>(x);
    transpose_w<<<dim3(96, 32), dim3(32, 8)>>>(W_attn, wah, 3*Cdim);
    param_kernel<<<256, 256>>>(x, W_param, b_param);
    mma_gemm<1><<<dim3(24, 64), 256, SMEM_MMA>>>(xh, xl, wah, b_attn, nullptr);
    normalize_qk<<<1024, 256>>>();
    scan_kernel<<<64, 512>>>(w, bb);
    transpose_w<<<dim3(32, 32), dim3(32, 8)>>>(W_proj, wph, Cdim);
    ln_split_o<<<512, 256>>>(w, bb);
    mma_gemm<0><<<dim3(8, 64), 256, SMEM_MMA>>>(oh, ol, wph, b_proj, out);
}

// round 9
// speedup vs baseline: 1.0030x; 1.0030x over previous
#include <cuda_runtime.h>
#include <cuda_fp16.h>
#include <math.h>
#include <stdint.h>

typedef unsigned long long ull;

#define Bdim 4
#define Tdim 2048
#define Cdim 1024
#define Hdim 16
#define Ddim 64
#define CSdim 16
#define NTdim (Tdim/CSdim)          // 128 chunks
#define BTdim (Bdim*Tdim)           // 8192
#define BHT   (Bdim*Hdim*Tdim)      // 131072
#define EPSLN 1e-5f

// ---------------- device scratch (allocation-free rule) ----------------
__device__ float g_qkv[3][(size_t)BHT*Ddim];           // q,k,v  [b,h,t,d] fp32
__device__ float g_param[3][BHT];                      // theta/alpha/eta
__device__ float g_o[(size_t)BTdim*Cdim];              // raw scan output [b,t,c]
__device__ __half g_xh[(size_t)BTdim*Cdim];            // x hi/lo fp16 [M,K]
__device__ __half g_xl[(size_t)BTdim*Cdim];
__device__ __half g_wah[(size_t)3*Cdim*Cdim];          // W_attn^T fp16 [N,K]
__device__ __half g_wph[(size_t)Cdim*Cdim];            // W_proj^T fp16 [N,K]
__device__ __half g_oh[(size_t)BTdim*Cdim];            // o hi/lo fp16 [M,K]
__device__ __half g_ol[(size_t)BTdim*Cdim];

// ---------------- helpers ----------------
__device__ __forceinline__ uint32_t smem_u32(const void* p) {
    return (uint32_t)__cvta_generic_to_shared(p);
}
#define SWZ128(off) ((off) ^ (((off) >> 3) & 0x70))

__device__ __forceinline__ void cpasync16(uint32_t smem_dst, const void* gmem_src) {
    asm volatile("cp.async.ca.shared.global [%0], [%1], 16;" :: "r"(smem_dst), "l"(gmem_src) : "memory");
}
__device__ __forceinline__ void cpcommit()  { asm volatile("cp.async.commit_group;" ::: "memory"); }
__device__ __forceinline__ void cpwait1()   { asm volatile("cp.async.wait_group 1;" ::: "memory"); }
__device__ __forceinline__ void cpwait0()   { asm volatile("cp.async.wait_group 0;" ::: "memory"); }

__device__ __forceinline__ void ldmx4(uint32_t addr, uint32_t& r0, uint32_t& r1,
                                      uint32_t& r2, uint32_t& r3) {
    asm volatile("ldmatrix.sync.aligned.m8n8.x4.shared.b16 {%0,%1,%2,%3}, [%4];"
                 : "=r"(r0), "=r"(r1), "=r"(r2), "=r"(r3) : "r"(addr));
}
__device__ __forceinline__ void mma16816(float* c, uint32_t a0, uint32_t a1,
                                         uint32_t a2, uint32_t a3,
                                         uint32_t b0, uint32_t b1) {
    asm volatile("mma.sync.aligned.m16n8k16.row.col.f32.f16.f16.f32 "
                 "{%0,%1,%2,%3}, {%4,%5,%6,%7}, {%8,%9}, {%0,%1,%2,%3};"
                 : "+f"(c[0]), "+f"(c[1]), "+f"(c[2]), "+f"(c[3])
                 : "r"(a0), "r"(a1), "r"(a2), "r"(a3), "r"(b0), "r"(b1));
}

// ---------------------------------------------------------------------------
// convert_x: fp32 -> fp16 hi/lo split
// ---------------------------------------------------------------------------
__global__ __launch_bounds__(256) void convert_x(const float* __restrict__ x)
{
    size_t i = (size_t)blockIdx.x * 1024 + threadIdx.x * 4;
    float4 v = *(const float4*)(x + i);
    __half h0 = __float2half(v.x);
    __half h1 = __float2half(v.y);
    __half h2 = __float2half(v.z);
    __half h3 = __float2half(v.w);
    __half2* ph = (__half2*)(g_xh + i);
    __half2* pl = (__half2*)(g_xl + i);
    ph[0] = __half2(h0, h1);
    ph[1] = __half2(h2, h3);
    pl[0] = __half2(__float2half(v.x - __half2float(h0)),
                    __float2half(v.y - __half2float(h1)));
    pl[1] = __half2(__float2half(v.z - __half2float(h2)),
                    __float2half(v.w - __half2float(h3)));
}

// ---------------------------------------------------------------------------
// transpose W [K][N] fp32 -> WT fp16 [N][K]
// ---------------------------------------------------------------------------
__global__ __launch_bounds__(256) void transpose_w(const float* __restrict__ W,
                                                   __half* __restrict__ WTh,
                                                   int Nfull)
{
    __shared__ float tile[32][33];
    int n0 = blockIdx.x * 32, k0 = blockIdx.y * 32;
    int tx = threadIdx.x, ty = threadIdx.y;   // block (32,8)
#pragma unroll
    for (int i = 0; i < 32; i += 8)
        tile[ty + i][tx] = W[(size_t)(k0 + ty + i) * Nfull + n0 + tx];
    __syncthreads();
#pragma unroll
    for (int i = 0; i < 32; i += 8)
        WTh[(size_t)(n0 + ty + i) * Cdim + k0 + tx] = __float2half(tile[tx][ty + i]);
}

// ---------------------------------------------------------------------------
// HMMA GEMM: D = Ah@B^T + Al@B^T (fp16, fp32 accum). CTA 128x128, 256 thr,
// 3-stage cp.async pipeline, ONE barrier per k-chunk.
// ---------------------------------------------------------------------------
#define NCHUNK 32
#define TILE_B 16384

template<int MODE>
__global__ __launch_bounds__(256) void mma_gemm(const __half* __restrict__ Ah,
                                                const __half* __restrict__ Al,
                                                const __half* __restrict__ Bh,
                                                const float* __restrict__ bias,
                                                float* __restrict__ out)
{
    extern __shared__ char smem[];
    __shared__ float bias_s[128];
    uint32_t base = (smem_u32(smem) + 1023) & ~1023u;
    uint32_t Aof[3], Bof[3];
#pragma unroll
    for (int s = 0; s < 3; s++) { Aof[s] = base + s*2*TILE_B; Bof[s] = Aof[s] + TILE_B; }

    int tid = threadIdx.x;
    int wid = tid >> 5, lane = tid & 31;
    int wm = wid & 3, wn = wid >> 2;
    int row0 = blockIdx.y * 128, col0 = blockIdx.x * 128;

    if (tid < 128) bias_s[tid] = bias[col0 + tid];

    auto load_chunk = [&](int ci, int slot) {
        int p = ci >> 4;
        int kk0 = (ci & 15) * 64;
        const __half* As = p ? Al : Ah;
#pragma unroll
        for (int j = 0; j < 4; j++) {
            int id = tid + j * 256;
            int r = id >> 3, u = id & 7;
            uint32_t off = (uint32_t)(r * 128 + u * 16);
            cpasync16(Aof[slot] + SWZ128(off), As + (size_t)(row0 + r) * Cdim + kk0 + u * 8);
        }
#pragma unroll
        for (int j = 0; j < 4; j++) {
            int id = tid + j * 256;
            int r = id >> 3, u = id & 7;
            uint32_t off = (uint32_t)(r * 128 + u * 16);
            cpasync16(Bof[slot] + SWZ128(off), Bh + (size_t)(col0 + r) * Cdim + kk0 + u * 8);
        }
        cpcommit();
    };

    float acc[2][8][4];
#pragma unroll
    for (int mt = 0; mt < 2; mt++)
#pragma unroll
        for (int nt = 0; nt < 8; nt++)
#pragma unroll
            for (int q = 0; q < 4; q++) acc[mt][nt][q] = 0.f;

    int a_row = wm * 32 + (lane & 15);
    int a_kb  = (lane >> 4) * 16;
    int b_row = wn * 64 + (lane & 7) + ((lane >> 4) << 3);
    int b_kb  = ((lane >> 3) & 1) * 16;

    load_chunk(0, 0);
    load_chunk(1, 1);

    for (int ci = 0; ci < NCHUNK; ci++) {
        cpwait1();            // stage ci resident (<=1 group pending: ci+1)
        __syncthreads();      // all warps done with stage ci-1 -> its slot reusable
        if (ci + 2 < NCHUNK) load_chunk(ci + 2, (ci + 2) % 3);
        else                 cpcommit();   // keep group accounting uniform
        int s = ci % 3;

#pragma unroll
        for (int kk = 0; kk < 4; kk++) {
            uint32_t a[2][4];
#pragma unroll
            for (int mt = 0; mt < 2; mt++) {
                uint32_t off = (uint32_t)((a_row + mt*16) * 128 + kk*32 + a_kb);
                ldmx4(Aof[s] + SWZ128(off), a[mt][0], a[mt][1], a[mt][2], a[mt][3]);
            }
            uint32_t bfr[4][4];
#pragma unroll
            for (int nt2 = 0; nt2 < 4; nt2++) {
                uint32_t off = (uint32_t)((b_row + nt2*16) * 128 + kk*32 + b_kb);
                ldmx4(Bof[s] + SWZ128(off), bfr[nt2][0], bfr[nt2][1], bfr[nt2][2], bfr[nt2][3]);
            }
#pragma unroll
            for (int mt = 0; mt < 2; mt++)
#pragma unroll
                for (int nt = 0; nt < 8; nt++) {
                    int nt2 = nt >> 1, hi = (nt & 1) << 1;
                    mma16816(acc[mt][nt], a[mt][0], a[mt][1], a[mt][2], a[mt][3],
                             bfr[nt2][hi], bfr[nt2][hi + 1]);
                }
        }
    }

    int rbase = row0 + wm * 32 + (lane >> 2);
    if (MODE == 1) {
        int gcb = col0 + wn * 64;
        int kind = gcb >> 10;
        int h2 = (gcb & 1023) >> 6;
#pragma unroll
        for (int mt = 0; mt < 2; mt++) {
#pragma unroll
            for (int half = 0; half < 2; half++) {
                int r = rbase + mt*16 + half*8;
                int b = r >> 11, t = r & 2047;
                float* dst = &g_qkv[kind][(((size_t)b*Hdim + h2)*Tdim + t)*Ddim];
#pragma unroll
                for (int nt = 0; nt < 8; nt++) {
                    int cd = nt*8 + (lane & 3)*2;
                    float2 v;
                    v.x = acc[mt][nt][half*2 + 0] + bias_s[wn*64 + cd + 0];
                    v.y = acc[mt][nt][half*2 + 1] + bias_s[wn*64 + cd + 1];
                    *(float2*)(dst + cd) = v;
                }
            }
        }
    } else {
#pragma unroll
        for (int mt = 0; mt < 2; mt++) {
#pragma unroll
            for (int half = 0; half < 2; half++) {
                int r = rbase + mt*16 + half*8;
                float* dst = out + (size_t)r * Cdim + col0 + wn*64;
#pragma unroll
                for (int nt = 0; nt < 8; nt++) {
                    int cd = nt*8 + (lane & 3)*2;
                    float2 v;
                    v.x = acc[mt][nt][half*2 + 0] + bias_s[wn*64 + cd + 0];
                    v.y = acc[mt][nt][half*2 + 1] + bias_s[wn*64 + cd + 1];
                    *(float2*)(dst + cd) = v;
                }
            }
        }
    }
}

// ---------------------------------------------------------------------------
// normalize_qk: row-wise L2 normalization of q and k (fully parallel).
// One thread per 64-float row. 262144 rows total.
// ---------------------------------------------------------------------------
__global__ __launch_bounds__(256) void normalize_qk()
{
    int idx = blockIdx.x * 256 + threadIdx.x;
    int tensor = idx >> 17;                  // 131072 rows per tensor
    int row = idx & (BHT - 1);
    float* p = g_qkv[tensor] + (size_t)row * Ddim;
    float4 v[16];
#pragma unroll
    for (int i = 0; i < 16; i++) v[i] = *(const float4*)(p + i*4);
    float ss = 0.f;
#pragma unroll
    for (int i = 0; i < 16; i++)
        ss += v[i].x*v[i].x + v[i].y*v[i].y + v[i].z*v[i].z + v[i].w*v[i].w;
    float sc = 1.f / fmaxf(sqrtf(ss), 1e-12f);
#pragma unroll
    for (int i = 0; i < 16; i++) {
        v[i].x *= sc; v[i].y *= sc; v[i].z *= sc; v[i].w *= sc;
        *(float4*)(p + i*4) = v[i];
    }
}

// ---------------------------------------------------------------------------
// ln_split_o: LayerNorm(o) per (b,t,h) row + fp16 hi/lo split.
// One thread per 64-float row. 131072 rows.
// ---------------------------------------------------------------------------
__global__ __launch_bounds__(256) void ln_split_o(const float* __restrict__ w,
                                                  const float* __restrict__ bln)
{
    __shared__ float w_s[1024], b_s[1024];
    int tid = threadIdx.x;
#pragma unroll
    for (int i = tid; i < 1024; i += 256) { w_s[i] = w[i]; b_s[i] = bln[i]; }
    __syncthreads();

    int r = blockIdx.x * 256 + tid;          // row id; h = r & 15
    int h = r & 15;
    const float* src = g_o + (size_t)r * 64;
    float4 xv[16];
#pragma unroll
    for (int i = 0; i < 16; i++) xv[i] = *(const float4*)(src + i*4);
    float s = 0.f;
#pragma unroll
    for (int i = 0; i < 16; i++) s += xv[i].x + xv[i].y + xv[i].z + xv[i].w;
    float mu = s * (1.f/64.f);
    float vv = 0.f;
#pragma unroll
    for (int i = 0; i < 16; i++) {
        float a = xv[i].x-mu, b2 = xv[i].y-mu, c = xv[i].z-mu, d = xv[i].w-mu;
        vv += a*a + b2*b2 + c*c + d*d;
    }
    float rstd = rsqrtf(vv * (1.f/64.f) + EPSLN);

    size_t base = (size_t)r * 64;
    const float* wp = w_s + h*64;
    const float* bp = b_s + h*64;
#pragma unroll
    for (int g8 = 0; g8 < 8; g8++) {
        float y[8];
        float4 a = xv[g8*2], b4 = xv[g8*2+1];
        float xs[8] = {a.x,a.y,a.z,a.w,b4.x,b4.y,b4.z,b4.w};
#pragma unroll
        for (int j = 0; j < 8; j++)
            y[j] = (xs[j]-mu)*rstd*wp[g8*8+j] + bp[g8*8+j];
        uint4 uh, ul;
        __half hh[8], lo[8];
#pragma unroll
        for (int j = 0; j < 8; j++) {
            hh[j] = __float2half(y[j]);
            lo[j] = __float2half(y[j] - __half2float(hh[j]));
        }
        __half2 h01 = __halves2half2(hh[0],hh[1]), h23 = __halves2half2(hh[2],hh[3]);
        __half2 h45 = __halves2half2(hh[4],hh[5]), h67 = __halves2half2(hh[6],hh[7]);
        __half2 l01 = __halves2half2(lo[0],lo[1]), l23 = __halves2half2(lo[2],lo[3]);
        __half2 l45 = __halves2half2(lo[4],lo[5]), l67 = __halves2half2(lo[6],lo[7]);
        uh.x = *(uint32_t*)&h01; uh.y = *(uint32_t*)&h23;
        uh.z = *(uint32_t*)&h45; uh.w = *(uint32_t*)&h67;
        ul.x = *(uint32_t*)&l01; ul.y = *(uint32_t*)&l23;
        ul.z = *(uint32_t*)&l45; ul.w = *(uint32_t*)&l67;
        *(uint4*)(g_oh + base + g8*8) = uh;
        *(uint4*)(g_ol + base + g8*8) = ul;
    }
}

// ---------------------------------------------------------------------------
// K2: p = sigmoid(x @ W_param + b_param). 256 blocks x 32 rows.
// ---------------------------------------------------------------------------
__global__ __launch_bounds__(256) void param_kernel(const float* __restrict__ x,
                                                    const float* __restrict__ W,
                                                    const float* __restrict__ bias)
{
    __shared__ float xs[32][68];
    __shared__ float Ws[64][48];
    int tid = threadIdx.x;
    int row0 = blockIdx.x * 32;
    int r = tid >> 3, q = tid & 7;

    float acc[6];
#pragma unroll
    for (int j = 0; j < 6; j++) acc[j] = 0.f;

    for (int kt = 0; kt < Cdim; kt += 64) {
        int lr = tid >> 3;
        int lc0 = (tid & 7) * 8;
#pragma unroll
        for (int tt = 0; tt < 2; tt++) {
            float4 v = *(const float4*)(x + (size_t)(row0 + lr) * Cdim + kt + lc0 + tt*4);
            xs[lr][lc0 + tt*4 + 0] = v.x;
            xs[lr][lc0 + tt*4 + 1] = v.y;
            xs[lr][lc0 + tt*4 + 2] = v.z;
            xs[lr][lc0 + tt*4 + 3] = v.w;
        }
#pragma unroll
        for (int tt = 0; tt < 12; tt++) {
            int idx = tid + tt * 256;
            int wr = idx / 48, wc = idx % 48;
            Ws[wr][wc] = W[(size_t)(kt + wr) * 48 + wc];
        }
        __syncthreads();
#pragma unroll
        for (int kk = 0; kk < 64; kk++) {
            float xv = xs[r][kk];
#pragma unroll
            for (int j = 0; j < 6; j++) acc[j] += xv * Ws[kk][q + 8*j];
        }
        __syncthreads();
    }
    int grow = row0 + r;
    int b = grow / Tdim, t = grow % Tdim;
#pragma unroll
    for (int j = 0; j < 6; j++) {
        int col = q + 8*j;
        int h = col / 3, ii = col % 3;
        float v = acc[j] + bias[col];
        v = 1.f / (1.f + expf(-v));
        g_param[ii][((size_t)b*Hdim + h)*Tdim + t] = v;
    }
}

// ---------------------------------------------------------------------------
// K3: chunked Titans scan — q/k pre-normalized, o written raw.
// ---------------------------------------------------------------------------
__device__ __forceinline__ ull pk1(float v) {
    ull r; asm("mov.b64 %0, {%1, %1};" : "=l"(r) : "f"(v)); return r;
}
__device__ __forceinline__ ull fma2(ull a, ull b, ull c) {
    ull d; asm("fma.rn.f32x2 %0, %1, %2, %3;" : "=l"(d) : "l"(a), "l"(b), "l"(c)); return d;
}
__device__ __forceinline__ ull mul2(ull a, ull b) {
    ull d; asm("mul.rn.f32x2 %0, %1, %2;" : "=l"(d) : "l"(a), "l"(b)); return d;
}
__device__ __forceinline__ float2 upk(ull v) {
    float2 f; asm("mov.b64 {%0, %1}, %2;" : "=f"(f.x), "=f"(f.y) : "l"(v)); return f;
}

#define CHUNK_F (CSdim*Ddim)
#define BUF_F   (3*CHUNK_F + 48)

__global__ __launch_bounds__(512) void scan_kernel(const float* __restrict__ w,
                                                   const float* __restrict__ bln)
{
    __shared__ __align__(16) float buf[2][BUF_F];
    __shared__ float kh_s[16][64], dkh_s[16][64], o_s[16][64];
    __shared__ float w_s[64], b_s[64];

    int tid  = threadIdx.x;
    int e    = tid >> 3, g = tid & 7;
    int lane = tid & 31, wid = tid >> 5;
    int bh = blockIdx.x;
    int b  = bh >> 4, h = bh & 15;

    const float* qg = g_qkv[0] + (size_t)bh * Tdim * Ddim;
    const float* kg = g_qkv[1] + (size_t)bh * Tdim * Ddim;
    const float* vg = g_qkv[2] + (size_t)bh * Tdim * Ddim;
    const float* thg = g_param[0] + (size_t)bh * Tdim;
    const float* alg = g_param[1] + (size_t)bh * Tdim;
    const float* etg = g_param[2] + (size_t)bh * Tdim;

    if (tid < 64) { w_s[tid] = w[h*64 + tid]; b_s[tid] = bln[h*64 + tid]; }

    ull S2[4], m2[4];
#pragma unroll
    for (int i = 0; i < 4; i++) { S2[i] = 0ull; m2[i] = 0ull; }

#define PREFETCH(ci, dst)                                                     \
    do {                                                                      \
        int base4 = (ci) * (CHUNK_F/4);                                       \
        for (int idx = tid; idx < 780; idx += 512) {                          \
            if (idx < 256)                                                    \
                cpasync16(smem_u32((dst) + idx*4), (const float4*)kg + base4 + idx); \
            else if (idx < 512)                                               \
                cpasync16(smem_u32((dst) + CHUNK_F + (idx-256)*4),            \
                          (const float4*)qg + base4 + (idx-256));             \
            else if (idx < 768)                                               \
                cpasync16(smem_u32((dst) + 2*CHUNK_F + (idx-512)*4),          \
                          (const float4*)vg + base4 + (idx-512));             \
            else if (idx < 772)                                               \
                cpasync16(smem_u32((dst) + 3*CHUNK_F + (idx-768)*4),          \
                          (const float4*)(thg + (ci)*16) + (idx-768));        \
            else if (idx < 776)                                               \
                cpasync16(smem_u32((dst) + 3*CHUNK_F + 16 + (idx-772)*4),     \
                          (const float4*)(alg + (ci)*16) + (idx-772));        \
            else                                                              \
                cpasync16(smem_u32((dst) + 3*CHUNK_F + 32 + (idx-776)*4),     \
                          (const float4*)(etg + (ci)*16) + (idx-776));        \
        }                                                                     \
        cpcommit();                                                           \
    } while (0)

    PREFETCH(0, buf[0]);

    for (int ci = 0; ci < NTdim; ci++) {
        if (ci + 1 < NTdim) {
            PREFETCH(ci + 1, buf[(ci+1) & 1]);
            cpwait1();
        } else {
            cpwait0();
        }
        __syncthreads();

        float* Kp = buf[ci & 1];
        float* Qp = Kp + CHUNK_F;
        float* Vp = Kp + 2*CHUNK_F;
        float* TH = Kp + 3*CHUNK_F;
        float* AL = TH + 16;
        float* ET = TH + 32;

        // kh = k @ S (packed partials + width-8 reduce)
#pragma unroll
        for (int c = 0; c < 16; c++) {
            ulonglong2 ka = *(const ulonglong2*)&Kp[c*64 + 8*g];
            ulonglong2 kb = *(const ulonglong2*)&Kp[c*64 + 8*g + 4];
            ull p2 = 0ull;
            p2 = fma2(ka.x, S2[0], p2);
            p2 = fma2(ka.y, S2[1], p2);
            p2 = fma2(kb.x, S2[2], p2);
            p2 = fma2(kb.y, S2[3], p2);
            float2 pf = upk(p2);
            float p = pf.x + pf.y;
            p += __shfl_xor_sync(0xffffffffu, p, 1);
            p += __shfl_xor_sync(0xffffffffu, p, 2);
            p += __shfl_xor_sync(0xffffffffu, p, 4);
            if (g == 0) kh_s[c][e] = p;
        }
        __syncthreads();

        // LN fwd + bwd per row
        {
            int c = wid;
            float x0 = kh_s[c][lane], x1 = kh_s[c][lane+32];
            float s = x0 + x1;
#pragma unroll
            for (int off = 16; off; off >>= 1) s += __shfl_xor_sync(0xffffffffu, s, off);
            float mu = s * (1.f/64.f);
            float xc0 = x0 - mu, xc1 = x1 - mu;
            float vv = xc0*xc0 + xc1*xc1;
#pragma unroll
            for (int off = 16; off; off >>= 1) vv += __shfl_xor_sync(0xffffffffu, vv, off);
            float rstd = rsqrtf(vv * (1.f/64.f) + EPSLN);
            float xh0 = xc0 * rstd, xh1 = xc1 * rstd;
            float w0 = w_s[lane], w1 = w_s[lane+32];
            float y0 = xh0*w0 + b_s[lane], y1 = xh1*w1 + b_s[lane+32];
            float dy0 = 2.f*(y0 - Vp[c*64 + lane]);
            float dy1 = 2.f*(y1 - Vp[c*64 + lane + 32]);
            float wdy0 = dy0*w0, wdy1 = dy1*w1;
            float c1 = xh0*wdy0 + xh1*wdy1;
            float c2 = wdy0 + wdy1;
#pragma unroll
            for (int off = 16; off; off >>= 1) {
                c1 += __shfl_xor_sync(0xffffffffu, c1, off);
                c2 += __shfl_xor_sync(0xffffffffu, c2, off);
            }
            c1 *= (1.f/64.f); c2 *= (1.f/64.f);
            dkh_s[c][lane]    = (wdy0 - xh0*c1 - c2) * rstd;
            dkh_s[c][lane+32] = (wdy1 - xh1*c1 - c2) * rstd;
        }
        __syncthreads();

        // token scan: state in packed registers
#pragma unroll 4
        for (int c = 0; c < 16; c++) {
            float th = TH[c], al = AL[c], et = ET[c];
            float dk = dkh_s[c][e];
            ulonglong2 ka = *(const ulonglong2*)&Kp[c*64 + 8*g];
            ulonglong2 kb = *(const ulonglong2*)&Kp[c*64 + 8*g + 4];
            ulonglong2 qa = *(const ulonglong2*)&Qp[c*64 + 8*g];
            ulonglong2 qb = *(const ulonglong2*)&Qp[c*64 + 8*g + 4];
            ull kp[4] = {ka.x, ka.y, kb.x, kb.y};
            ull qp[4] = {qa.x, qa.y, qb.x, qb.y};
            ull et2  = pk1(et);
            ull oma2 = pk1(1.f - al);
            ull ntd2 = pk1(-th * dk);
            ull po2 = 0ull;
#pragma unroll
            for (int j = 0; j < 4; j++) {
                m2[j] = fma2(et2, m2[j], mul2(ntd2, kp[j]));
                S2[j] = fma2(oma2, S2[j], m2[j]);
                po2   = fma2(qp[j], S2[j], po2);
            }
            float2 pf = upk(po2);
            float po = pf.x + pf.y;
            po += __shfl_xor_sync(0xffffffffu, po, 1);
            po += __shfl_xor_sync(0xffffffffu, po, 2);
            po += __shfl_xor_sync(0xffffffffu, po, 4);
            if (g == 0) o_s[c][e] = po;
        }
        __syncthreads();

        // coalesced raw o write: warp wid handles row wid
        {
            int c = wid;
            int t = ci*16 + c;
            float2 v = *(const float2*)&o_s[c][lane*2];
            *(float2*)(g_o + ((size_t)b*Tdim + t)*Cdim + h*64 + lane*2) = v;
        }
    }
#undef PREFETCH
}

// ---------------------------------------------------------------------------
extern "C" void kernel_launch(void* const* d_in, const int* in_sizes, int n_in,
                              void* d_out, int out_size)
{
    const float* x       = (const float*)d_in[0];
    const float* W_attn  = (const float*)d_in[1];
    const float* b_attn  = (const float*)d_in[2];
    const float* W_param = (const float*)d_in[3];
    const float* b_param = (const float*)d_in[4];
    const float* W_proj  = (const float*)d_in[5];
    const float* b_proj  = (const float*)d_in[6];
    const float* w       = (const float*)d_in[7];
    const float* bb      = (const float*)d_in[8];
    float* out = (float*)d_out;

    const int SMEM_MMA = 1024 + 6*TILE_B;   // 3-stage, ~97KB
    cudaFuncSetAttribute(mma_gemm<1>, cudaFuncAttributeMaxDynamicSharedMemorySize, SMEM_MMA);
    cudaFuncSetAttribute(mma_gemm<0>, cudaFuncAttributeMaxDynamicSharedMemorySize, SMEM_MMA);

    __half *xh, *xl, *wah, *wph, *oh, *ol;
    cudaGetSymbolAddress((void**)&xh,  g_xh);
    cudaGetSymbolAddress((void**)&xl,  g_xl);
    cudaGetSymbolAddress((void**)&wah, g_wah);
    cudaGetSymbolAddress((void**)&wph, g_wph);
    cudaGetSymbolAddress((void**)&oh,  g_oh);
    cudaGetSymbolAddress((void**)&ol,  g_ol);

    convert_x<<<(BTdim*Cdim)/1024, 256>>>(x);
    transpose_w<<<dim3(96, 32), dim3(32, 8)>>>(W_attn, wah, 3*Cdim);
    param_kernel<<<256, 256>>>(x, W_param, b_param);
    mma_gemm<1><<<dim3(24, 64), 256, SMEM_MMA>>>(xh, xl, wah, b_attn, nullptr);
    normalize_qk<<<1024, 256>>>();
    scan_kernel<<<64, 512>>>(w, bb);
    transpose_w<<<dim3(32, 32), dim3(32, 8)>>>(W_proj, wph, Cdim);
    ln_split_o<<<512, 256>>>(w, bb);
    mma_gemm<0><<<dim3(8, 64), 256, SMEM_MMA>>>(oh, ol, wph, b_proj, out);
}